// round 2
// baseline (speedup 1.0000x reference)
#include <cuda_runtime.h>
#include <cuda_bf16.h>

#define N_NODES 50000
#define N_EDGES 800000
#define DIMS 128

// Scratch: per-node projections (no cudaMalloc allowed).
__device__ float g_psrc[N_NODES];
__device__ float g_pdst[N_NODES];

// Kernel 1: one warp per node. Each lane loads float4 of the node row and of
// both weight halves, computes partial dots, warp-reduces, writes scalars.
__global__ void proj_kernel(const float* __restrict__ h,
                            const float* __restrict__ W,
                            const float* __restrict__ b) {
    int gwarp = (blockIdx.x * blockDim.x + threadIdx.x) >> 5;
    int lane  = threadIdx.x & 31;
    if (gwarp >= N_NODES) return;

    const float4* hrow = reinterpret_cast<const float4*>(h + (size_t)gwarp * DIMS);
    const float4* ws   = reinterpret_cast<const float4*>(W);          // W[0:128]
    const float4* wd   = reinterpret_cast<const float4*>(W + DIMS);   // W[128:256]

    float4 hv  = hrow[lane];
    float4 wsv = ws[lane];
    float4 wdv = wd[lane];

    float s = hv.x * wsv.x + hv.y * wsv.y + hv.z * wsv.z + hv.w * wsv.w;
    float d = hv.x * wdv.x + hv.y * wdv.y + hv.z * wdv.z + hv.w * wdv.w;

    #pragma unroll
    for (int o = 16; o > 0; o >>= 1) {
        s += __shfl_xor_sync(0xffffffffu, s, o);
        d += __shfl_xor_sync(0xffffffffu, d, o);
    }

    if (lane == 0) {
        g_psrc[gwarp] = s;
        g_pdst[gwarp] = d + b[0];
    }
}

// Kernel 2: 4 edges per thread, int4 index loads, float4 output store.
// Indices are INT32 (JAX downgrades int64 without x64 enabled).
// Gather tables (200 KB each) are L2-resident.
__global__ void gather_kernel(const int* __restrict__ src,
                              const int* __restrict__ dst,
                              float* __restrict__ out) {
    int i = blockIdx.x * blockDim.x + threadIdx.x;   // quad index
    if (i >= N_EDGES / 4) return;
    int4 s4 = reinterpret_cast<const int4*>(src)[i];
    int4 d4 = reinterpret_cast<const int4*>(dst)[i];
    float4 o;
    o.x = g_psrc[s4.x] + g_pdst[d4.x];
    o.y = g_psrc[s4.y] + g_pdst[d4.y];
    o.z = g_psrc[s4.z] + g_pdst[d4.z];
    o.w = g_psrc[s4.w] + g_pdst[d4.w];
    reinterpret_cast<float4*>(out)[i] = o;
}

extern "C" void kernel_launch(void* const* d_in, const int* in_sizes, int n_in,
                              void* d_out, int out_size) {
    const float* h   = (const float*)d_in[0];
    const int*   src = (const int*)d_in[1];
    const int*   dst = (const int*)d_in[2];
    const float* W   = (const float*)d_in[3];
    const float* b   = (const float*)d_in[4];
    float* out = (float*)d_out;

    // Projection: 50000 warps, 8 warps (256 threads) per block.
    {
        int warps_per_block = 8;
        int blocks = (N_NODES + warps_per_block - 1) / warps_per_block;
        proj_kernel<<<blocks, warps_per_block * 32>>>(h, W, b);
    }

    // Gather: 200000 threads (4 edges each; 800000 % 4 == 0).
    {
        int threads = 256;
        int quads = N_EDGES / 4;
        int blocks = (quads + threads - 1) / threads;
        gather_kernel<<<blocks, threads>>>(src, dst, out);
    }
}

// round 3
// speedup vs baseline: 1.0052x; 1.0052x over previous
#include <cuda_runtime.h>
#include <cuda_bf16.h>

#define N_NODES 50000
#define N_EDGES 800000
#define DIMS 128

// Scratch: per-node projections (no cudaMalloc allowed).
__device__ float g_psrc[N_NODES];
__device__ float g_pdst[N_NODES];

// Kernel 1: one warp per node. Each lane loads float4 of the node row and of
// both weight halves, computes partial dots, warp-reduces, writes scalars.
__global__ void proj_kernel(const float* __restrict__ h,
                            const float* __restrict__ W,
                            const float* __restrict__ b) {
    int gwarp = (blockIdx.x * blockDim.x + threadIdx.x) >> 5;
    int lane  = threadIdx.x & 31;
    if (gwarp >= N_NODES) return;

    const float4* hrow = reinterpret_cast<const float4*>(h + (size_t)gwarp * DIMS);
    const float4* ws   = reinterpret_cast<const float4*>(W);          // W[0:128]
    const float4* wd   = reinterpret_cast<const float4*>(W + DIMS);   // W[128:256]

    float4 hv  = hrow[lane];
    float4 wsv = ws[lane];
    float4 wdv = wd[lane];

    float s = hv.x * wsv.x + hv.y * wsv.y + hv.z * wsv.z + hv.w * wsv.w;
    float d = hv.x * wdv.x + hv.y * wdv.y + hv.z * wdv.z + hv.w * wdv.w;

    #pragma unroll
    for (int o = 16; o > 0; o >>= 1) {
        s += __shfl_xor_sync(0xffffffffu, s, o);
        d += __shfl_xor_sync(0xffffffffu, d, o);
    }

    if (lane == 0) {
        g_psrc[gwarp] = s;
        g_pdst[gwarp] = d + b[0];
    }
}

// Kernel 2: 4 edges per thread, int4 index loads, float4 output store.
// Indices are INT32 (JAX downgrades int64 without x64 enabled).
// Gather tables (200 KB each) are L2-resident.
__global__ void gather_kernel(const int* __restrict__ src,
                              const int* __restrict__ dst,
                              float* __restrict__ out) {
    int i = blockIdx.x * blockDim.x + threadIdx.x;   // quad index
    if (i >= N_EDGES / 4) return;
    int4 s4 = reinterpret_cast<const int4*>(src)[i];
    int4 d4 = reinterpret_cast<const int4*>(dst)[i];
    float4 o;
    o.x = g_psrc[s4.x] + g_pdst[d4.x];
    o.y = g_psrc[s4.y] + g_pdst[d4.y];
    o.z = g_psrc[s4.z] + g_pdst[d4.z];
    o.w = g_psrc[s4.w] + g_pdst[d4.w];
    reinterpret_cast<float4*>(out)[i] = o;
}

extern "C" void kernel_launch(void* const* d_in, const int* in_sizes, int n_in,
                              void* d_out, int out_size) {
    const float* h   = (const float*)d_in[0];
    const int*   src = (const int*)d_in[1];
    const int*   dst = (const int*)d_in[2];
    const float* W   = (const float*)d_in[3];
    const float* b   = (const float*)d_in[4];
    float* out = (float*)d_out;

    // Projection: 50000 warps, 8 warps (256 threads) per block.
    {
        int warps_per_block = 8;
        int blocks = (N_NODES + warps_per_block - 1) / warps_per_block;
        proj_kernel<<<blocks, warps_per_block * 32>>>(h, W, b);
    }

    // Gather: 200000 threads (4 edges each; 800000 % 4 == 0).
    {
        int threads = 256;
        int quads = N_EDGES / 4;
        int blocks = (quads + threads - 1) / threads;
        gather_kernel<<<blocks, threads>>>(src, dst, out);
    }
}

// round 4
// speedup vs baseline: 1.1270x; 1.1211x over previous
#include <cuda_runtime.h>
#include <cuda_bf16.h>

#define N_NODES 50000
#define N_EDGES 800000
#define DIMS 128

// Scratch: per-node projections (no cudaMalloc allowed).
__device__ float g_psrc[N_NODES];
__device__ float g_pdst[N_NODES];

// Kernel 1: one warp handles TWO nodes (doubles MLP on the streaming row
// loads). Each lane loads float4 of each node row + both weight halves,
// computes 4 partial dots, one 5-level shfl tree reduces all four.
__global__ void proj_kernel(const float* __restrict__ h,
                            const float* __restrict__ W,
                            const float* __restrict__ b) {
    int gwarp = (blockIdx.x * blockDim.x + threadIdx.x) >> 5;
    int lane  = threadIdx.x & 31;
    int n0 = gwarp * 2;
    if (n0 >= N_NODES) return;
    int n1 = n0 + 1;
    bool has1 = (n1 < N_NODES);

    const float4* ws = reinterpret_cast<const float4*>(W);          // W[0:128]
    const float4* wd = reinterpret_cast<const float4*>(W + DIMS);   // W[128:256]

    // Front-batch the two row loads (independent -> MLP_p1 = 2).
    float4 hv0 = reinterpret_cast<const float4*>(h + (size_t)n0 * DIMS)[lane];
    float4 hv1 = has1 ? reinterpret_cast<const float4*>(h + (size_t)n1 * DIMS)[lane]
                      : make_float4(0.f, 0.f, 0.f, 0.f);
    float4 wsv = ws[lane];
    float4 wdv = wd[lane];

    float s0 = hv0.x * wsv.x + hv0.y * wsv.y + hv0.z * wsv.z + hv0.w * wsv.w;
    float d0 = hv0.x * wdv.x + hv0.y * wdv.y + hv0.z * wdv.z + hv0.w * wdv.w;
    float s1 = hv1.x * wsv.x + hv1.y * wsv.y + hv1.z * wsv.z + hv1.w * wsv.w;
    float d1 = hv1.x * wdv.x + hv1.y * wdv.y + hv1.z * wdv.z + hv1.w * wdv.w;

    #pragma unroll
    for (int o = 16; o > 0; o >>= 1) {
        s0 += __shfl_xor_sync(0xffffffffu, s0, o);
        d0 += __shfl_xor_sync(0xffffffffu, d0, o);
        s1 += __shfl_xor_sync(0xffffffffu, s1, o);
        d1 += __shfl_xor_sync(0xffffffffu, d1, o);
    }

    if (lane == 0) {
        float bb = b[0];
        g_psrc[n0] = s0;
        g_pdst[n0] = d0 + bb;
        if (has1) {
            g_psrc[n1] = s1;
            g_pdst[n1] = d1 + bb;
        }
    }
}

// Kernel 2: 2 edges per thread -> 400k threads for full occupancy (the
// gather is latency-bound on random L1/L2 lookups; warp count is the
// hiding mechanism). int2 index loads, float2 output store, __ldg tables.
__global__ void gather_kernel(const int* __restrict__ src,
                              const int* __restrict__ dst,
                              float* __restrict__ out) {
    int i = blockIdx.x * blockDim.x + threadIdx.x;   // pair index
    if (i >= N_EDGES / 2) return;
    int2 s2 = reinterpret_cast<const int2*>(src)[i];
    int2 d2 = reinterpret_cast<const int2*>(dst)[i];
    float a0 = __ldg(&g_psrc[s2.x]);
    float b0 = __ldg(&g_pdst[d2.x]);
    float a1 = __ldg(&g_psrc[s2.y]);
    float b1 = __ldg(&g_pdst[d2.y]);
    float2 o;
    o.x = a0 + b0;
    o.y = a1 + b1;
    reinterpret_cast<float2*>(out)[i] = o;
}

extern "C" void kernel_launch(void* const* d_in, const int* in_sizes, int n_in,
                              void* d_out, int out_size) {
    const float* h   = (const float*)d_in[0];
    const int*   src = (const int*)d_in[1];
    const int*   dst = (const int*)d_in[2];
    const float* W   = (const float*)d_in[3];
    const float* b   = (const float*)d_in[4];
    float* out = (float*)d_out;

    // Projection: 25000 warps (2 nodes each), 8 warps per block.
    {
        int warps = (N_NODES + 1) / 2;
        int warps_per_block = 8;
        int blocks = (warps + warps_per_block - 1) / warps_per_block;
        proj_kernel<<<blocks, warps_per_block * 32>>>(h, W, b);
    }

    // Gather: 400000 threads (2 edges each; 800000 % 2 == 0).
    {
        int threads = 256;
        int pairs = N_EDGES / 2;
        int blocks = (pairs + threads - 1) / threads;
        gather_kernel<<<blocks, threads>>>(src, dst, out);
    }
}